// round 5
// baseline (speedup 1.0000x reference)
#include <cuda_runtime.h>
#include <math.h>

#define BB 16
#define NN 1024
#define IND 256
#define HH 4
#define DD 64
#define HD 256
#define EPSV 1e-5f

typedef unsigned long long u64;

// Scratch (no allocations allowed)
__device__ float g_h[BB * NN * HD];      // projected features [b,n,H*D]
__device__ float g_src[BB * NN * HH];    // src logits [b,n,H]
__device__ float g_dst[BB * NN * HH];    // dst logits [b,n,H]
__device__ float g_att[BB * NN * HD];    // attention output pre-LN

__device__ __forceinline__ void ffma2(u64& d, u64 a, u64 b) {
    asm("fma.rn.f32x2 %0, %1, %2, %0;" : "+l"(d) : "l"(a), "l"(b));
}
__device__ __forceinline__ u64 pack2(float v) {
    u64 r;
    unsigned int u = __float_as_uint(v);
    asm("mov.b64 %0, {%1, %1};" : "=l"(r) : "r"(u));
    return r;
}
__device__ __forceinline__ float2 unpack2(u64 v) {
    unsigned int lo, hi;
    asm("mov.b64 {%0, %1}, %2;" : "=r"(lo), "=r"(hi) : "l"(v));
    return make_float2(__uint_as_float(lo), __uint_as_float(hi));
}

// ---------------------------------------------------------------------------
// Kernel 1: h = x @ W  (M=16384, N=256, K=256) + fused src/dst head dots.
// Block (bm, bn): rows bm*64..+64, cols bn*64..+64 == head bn's 64 dims.
// ---------------------------------------------------------------------------
__global__ __launch_bounds__(256) void gemm_k(const float* __restrict__ A,
                                              const float* __restrict__ Wm,
                                              const float* __restrict__ asrc,
                                              const float* __restrict__ adst) {
    __shared__ float As[16][68];
    __shared__ float Bs[16][68];
    int bm = blockIdx.x;          // 256 tiles of 64 rows
    int bn = blockIdx.y;          // 4 tiles of 64 cols (== head)
    int tid = threadIdx.x;
    int tx = tid & 15, ty = tid >> 4;
    int arow = tid >> 2, acol = (tid & 3) * 4;
    int brow = tid >> 4, bcol = (tid & 15) * 4;
    const float* Ap = A + (size_t)(bm * 64 + arow) * IND;
    const float* Bp = Wm + (size_t)bn * 64;
    u64 acc2[4][2] = {};
    for (int k0 = 0; k0 < IND; k0 += 16) {
        float4 a4 = *(const float4*)(Ap + k0 + acol);
        As[acol + 0][arow] = a4.x;
        As[acol + 1][arow] = a4.y;
        As[acol + 2][arow] = a4.z;
        As[acol + 3][arow] = a4.w;
        float4 b4 = *(const float4*)(Bp + (size_t)(k0 + brow) * HD + bcol);
        *(float4*)&Bs[brow][bcol] = b4;
        __syncthreads();
#pragma unroll
        for (int kk = 0; kk < 16; kk++) {
            const u64* bp = (const u64*)&Bs[kk][tx * 4];
            u64 b0 = bp[0], b1 = bp[1];
#pragma unroll
            for (int i = 0; i < 4; i++) {
                u64 aa = pack2(As[kk][ty * 4 + i]);
                ffma2(acc2[i][0], aa, b0);
                ffma2(acc2[i][1], aa, b1);
            }
        }
        __syncthreads();
    }
    // unpack, store h, and fold in src/dst dot products for this head
    const float4 as4 = *(const float4*)(asrc + bn * 64 + tx * 4);
    const float4 ad4 = *(const float4*)(adst + bn * 64 + tx * 4);
#pragma unroll
    for (int i = 0; i < 4; i++) {
        float2 lo = unpack2(acc2[i][0]);
        float2 hi = unpack2(acc2[i][1]);
        int row = bm * 64 + ty * 4 + i;
        float* o = g_h + (size_t)row * HD + bn * 64 + tx * 4;
        *(float4*)o = make_float4(lo.x, lo.y, hi.x, hi.y);
        float s1 = lo.x * as4.x + lo.y * as4.y + hi.x * as4.z + hi.y * as4.w;
        float s2 = lo.x * ad4.x + lo.y * ad4.y + hi.x * ad4.z + hi.y * ad4.w;
#pragma unroll
        for (int o2 = 8; o2 > 0; o2 >>= 1) {
            s1 += __shfl_xor_sync(0xffffffffu, s1, o2);
            s2 += __shfl_xor_sync(0xffffffffu, s2, o2);
        }
        if (tx == 0) {
            g_src[(size_t)row * HH + bn] = s1;
            g_dst[(size_t)row * HH + bn] = s2;
        }
    }
}

// ---------------------------------------------------------------------------
// Kernel 2: fused scores + masked softmax (single-pass, no max-shift) + P@V
// One block = (batch b, head hh, 64-row i-tile). Streams 64-wide j-tiles.
// Scores are bounded (|e| < ~10) so exp(e) cannot overflow fp32.
// ---------------------------------------------------------------------------
__global__ __launch_bounds__(256) void attn_k(const int* __restrict__ adj,
                                              const int* __restrict__ mask) {
    __shared__ float Vt[64][68];      // V tile [j][d]
    __shared__ float Pt[64][68];      // unnormalized probs [i][j]
    __shared__ float dstS[64];
    __shared__ float srcS[64];
    __shared__ int mJ[64];
    __shared__ int mI[64];
    __shared__ float lS[64];

    int it = blockIdx.x, hh = blockIdx.y, b = blockIdx.z;
    int i0 = it * 64;
    int tid = threadIdx.x;
    int ti = tid >> 2, q = tid & 3;        // score-phase mapping: 4 threads/row
    int iy = tid >> 4, ix = tid & 15;      // accumulate mapping: 4x4 reg tile

    if (tid < 64) {
        srcS[tid] = g_src[(size_t)(b * NN + i0 + tid) * HH + hh];
        mI[tid] = mask[b * NN + i0 + tid];
        lS[tid] = 0.f;
    }
    u64 acc2[4][2] = {};
    const float* hb = g_h + (size_t)(b * NN) * HD + hh * DD;
    const int* adjb = adj + (size_t)(b * NN + i0) * NN;

    for (int j0 = 0; j0 < NN; j0 += 64) {
        // --- load V tile + dst/mask for this j tile ---
        {
            const float* vr = hb + (size_t)(j0 + ti) * HD + q * 16;
            float4 v0 = ((const float4*)vr)[0];
            float4 v1 = ((const float4*)vr)[1];
            float4 v2 = ((const float4*)vr)[2];
            float4 v3 = ((const float4*)vr)[3];
            float* vd = &Vt[ti][q * 16];
            ((float4*)vd)[0] = v0;
            ((float4*)vd)[1] = v1;
            ((float4*)vd)[2] = v2;
            ((float4*)vd)[3] = v3;
        }
        if (tid < 64) {
            dstS[tid] = g_dst[(size_t)(b * NN + j0 + tid) * HH + hh];
            mJ[tid] = mask[b * NN + j0 + tid];
        }
        __syncthreads();

        // --- score phase: row ti, 16 j's per thread; p = valid ? exp(e) : 0 ---
        {
            float si = srcS[ti];
            bool rv = mI[ti] > 0;
            const int4* arow = (const int4*)(adjb + (size_t)ti * NN + j0 + q * 16);
            float ls = 0.f;
            float* pr = &Pt[ti][q * 16];
#pragma unroll
            for (int k4 = 0; k4 < 4; k4++) {
                int4 a = arow[k4];
                int av[4] = {a.x, a.y, a.z, a.w};
                float4 p4;
                float pv[4];
#pragma unroll
                for (int c = 0; c < 4; c++) {
                    int jj = q * 16 + k4 * 4 + c;
                    float ev = si + dstS[jj];
                    ev = ev > 0.f ? ev : 0.2f * ev;
                    bool v = rv && (av[c] > 0) && (mJ[jj] > 0);
                    pv[c] = v ? __expf(ev) : 0.f;
                    ls += pv[c];
                }
                p4.x = pv[0]; p4.y = pv[1]; p4.z = pv[2]; p4.w = pv[3];
                ((float4*)pr)[k4] = p4;
            }
            ls += __shfl_xor_sync(0xffffffffu, ls, 1);
            ls += __shfl_xor_sync(0xffffffffu, ls, 2);
            if (q == 0) lS[ti] += ls;
        }
        __syncthreads();

        // --- accumulate: packed f32x2 FMA, rows iy*4+r, dims ix*4..+4 ---
#pragma unroll 4
        for (int kk = 0; kk < 64; kk++) {
            const u64* vp = (const u64*)&Vt[kk][ix * 4];
            u64 v0 = vp[0], v1 = vp[1];
#pragma unroll
            for (int r = 0; r < 4; r++) {
                u64 pp = pack2(Pt[iy * 4 + r][kk]);
                ffma2(acc2[r][0], pp, v0);
                ffma2(acc2[r][1], pp, v1);
            }
        }
        __syncthreads();
    }

    // --- epilogue: normalize by l, write out ---
#pragma unroll
    for (int r = 0; r < 4; r++) {
        int row = i0 + iy * 4 + r;
        float l = lS[iy * 4 + r];
        float inv = l > 0.f ? 1.0f / l : 0.f;
        float2 lo = unpack2(acc2[r][0]);
        float2 hi = unpack2(acc2[r][1]);
        float* o = g_att + (size_t)(b * NN + row) * HD + hh * DD + ix * 4;
        *(float4*)o = make_float4(lo.x * inv, lo.y * inv, hi.x * inv, hi.y * inv);
    }
}

// ---------------------------------------------------------------------------
// Kernel 3: out = LayerNorm(att * mask_i) * gamma + beta
// ---------------------------------------------------------------------------
__global__ __launch_bounds__(256) void ln_k(const int* __restrict__ mask,
                                            const float* __restrict__ gamma,
                                            const float* __restrict__ beta,
                                            float* __restrict__ out) {
    int row = blockIdx.x;  // 0..B*N-1
    int t = threadIdx.x;
    float mf = mask[row] > 0 ? 1.f : 0.f;
    float v = g_att[(size_t)row * HD + t] * mf;
    float s = v, s2 = v * v;
#pragma unroll
    for (int o = 16; o > 0; o >>= 1) {
        s += __shfl_xor_sync(0xffffffffu, s, o);
        s2 += __shfl_xor_sync(0xffffffffu, s2, o);
    }
    __shared__ float ws[8], ws2[8];
    int w = t >> 5, lane = t & 31;
    if (lane == 0) { ws[w] = s; ws2[w] = s2; }
    __syncthreads();
    float a = 0.f, bsum = 0.f;
#pragma unroll
    for (int i = 0; i < 8; i++) { a += ws[i]; bsum += ws2[i]; }
    float mu = a * (1.0f / HD);
    float var = bsum * (1.0f / HD) - mu * mu;
    out[(size_t)row * HD + t] = (v - mu) * rsqrtf(var + EPSV) * gamma[t] + beta[t];
}

// ---------------------------------------------------------------------------
extern "C" void kernel_launch(void* const* d_in, const int* in_sizes, int n_in,
                              void* d_out, int out_size) {
    const float* x = (const float*)d_in[0];
    const int* adj = (const int*)d_in[1];
    const int* mask = (const int*)d_in[2];
    const float* Wm = (const float*)d_in[3];
    const float* a_src = (const float*)d_in[4];
    const float* a_dst = (const float*)d_in[5];
    const float* gamma = (const float*)d_in[6];
    const float* beta = (const float*)d_in[7];
    float* out = (float*)d_out;

    dim3 gg(BB * NN / 64, HD / 64);
    gemm_k<<<gg, 256>>>(x, Wm, a_src, a_dst);
    dim3 ga(NN / 64, HH, BB);
    attn_k<<<ga, 256>>>(adj, mask);
    ln_k<<<BB * NN, 256>>>(mask, gamma, beta, out);
}

// round 6
// speedup vs baseline: 1.3275x; 1.3275x over previous
#include <cuda_runtime.h>
#include <math.h>

#define BB 16
#define NN 1024
#define IND 256
#define HH 4
#define DD 64
#define HD 256
#define EPSV 1e-5f
#define NEGBIG -1.0e30f

typedef unsigned long long u64;

// Scratch (no allocations allowed)
__device__ float g_h[BB * NN * HD];      // projected features [b,n,H*D]
__device__ float g_src[BB * NN * HH];    // src logits [b,n,H]
__device__ float g_dst[BB * NN * HH];    // dst logits [b,n,H]
__device__ float g_att[BB * NN * HD];    // attention output pre-LN

__device__ __forceinline__ void ffma2(u64& d, u64 a, u64 b) {
    asm("fma.rn.f32x2 %0, %1, %2, %0;" : "+l"(d) : "l"(a), "l"(b));
}
__device__ __forceinline__ u64 pack2(float v) {
    u64 r; unsigned u = __float_as_uint(v);
    asm("mov.b64 %0, {%1, %1};" : "=l"(r) : "r"(u));
    return r;
}
__device__ __forceinline__ float2 unpack2(u64 v) {
    unsigned lo, hi;
    asm("mov.b64 {%0, %1}, %2;" : "=r"(lo), "=r"(hi) : "l"(v));
    return make_float2(__uint_as_float(lo), __uint_as_float(hi));
}
// one LDS.128 directly into two u64 regs (no pack movs)
__device__ __forceinline__ void lds_v2u64(u64& a, u64& b, const void* p) {
    unsigned addr = (unsigned)__cvta_generic_to_shared(p);
    asm("ld.shared.v2.u64 {%0, %1}, [%2];" : "=l"(a), "=l"(b) : "r"(addr));
}

// ---------------------------------------------------------------------------
// Kernel 1: h = x @ W (M=16384,N=256,K=256), double-buffered, f32x2 FMA,
// fused src/dst head dot products in the epilogue (bn tile == head bn).
// ---------------------------------------------------------------------------
__global__ __launch_bounds__(256) void gemm_k(const float* __restrict__ A,
                                              const float* __restrict__ Wm,
                                              const float* __restrict__ asrc,
                                              const float* __restrict__ adst) {
    __shared__ float As[2][16][68];
    __shared__ float Bs[2][16][68];
    int bm = blockIdx.x, bn = blockIdx.y;
    int tid = threadIdx.x;
    int tx = tid & 15, ty = tid >> 4;
    int arow = tid >> 2, acol = (tid & 3) * 4;
    int brow = tid >> 4, bcol = (tid & 15) * 4;
    const float* Ap = A + (size_t)(bm * 64 + arow) * IND;
    const float* Bp = Wm + (size_t)bn * 64;
    u64 acc2[4][2] = {};

    float4 ra = *(const float4*)(Ap + acol);
    float4 rb = *(const float4*)(Bp + (size_t)brow * HD + bcol);
    As[0][acol + 0][arow] = ra.x;
    As[0][acol + 1][arow] = ra.y;
    As[0][acol + 2][arow] = ra.z;
    As[0][acol + 3][arow] = ra.w;
    *(float4*)&Bs[0][brow][bcol] = rb;
    __syncthreads();

    int cur = 0;
    for (int s = 0; s < 16; s++) {
        if (s < 15) {   // prefetch next k-slab while computing this one
            ra = *(const float4*)(Ap + (s + 1) * 16 + acol);
            rb = *(const float4*)(Bp + (size_t)((s + 1) * 16 + brow) * HD + bcol);
        }
#pragma unroll
        for (int kk = 0; kk < 16; kk++) {
            u64 b0, b1;
            lds_v2u64(b0, b1, &Bs[cur][kk][tx * 4]);
            float4 aa = *(const float4*)&As[cur][kk][ty * 4];
            u64 a0 = pack2(aa.x), a1 = pack2(aa.y), a2 = pack2(aa.z), a3 = pack2(aa.w);
            ffma2(acc2[0][0], a0, b0); ffma2(acc2[0][1], a0, b1);
            ffma2(acc2[1][0], a1, b0); ffma2(acc2[1][1], a1, b1);
            ffma2(acc2[2][0], a2, b0); ffma2(acc2[2][1], a2, b1);
            ffma2(acc2[3][0], a3, b0); ffma2(acc2[3][1], a3, b1);
        }
        if (s < 15) {
            int nxt = cur ^ 1;
            As[nxt][acol + 0][arow] = ra.x;
            As[nxt][acol + 1][arow] = ra.y;
            As[nxt][acol + 2][arow] = ra.z;
            As[nxt][acol + 3][arow] = ra.w;
            *(float4*)&Bs[nxt][brow][bcol] = rb;
            __syncthreads();
            cur = nxt;
        }
    }

    const float4 as4 = *(const float4*)(asrc + bn * 64 + tx * 4);
    const float4 ad4 = *(const float4*)(adst + bn * 64 + tx * 4);
#pragma unroll
    for (int i = 0; i < 4; i++) {
        float2 lo = unpack2(acc2[i][0]);
        float2 hi = unpack2(acc2[i][1]);
        int row = bm * 64 + ty * 4 + i;
        float* o = g_h + (size_t)row * HD + bn * 64 + tx * 4;
        *(float4*)o = make_float4(lo.x, lo.y, hi.x, hi.y);
        float s1 = lo.x * as4.x + lo.y * as4.y + hi.x * as4.z + hi.y * as4.w;
        float s2 = lo.x * ad4.x + lo.y * ad4.y + hi.x * ad4.z + hi.y * ad4.w;
#pragma unroll
        for (int o2 = 8; o2 > 0; o2 >>= 1) {
            s1 += __shfl_xor_sync(0xffffffffu, s1, o2);
            s2 += __shfl_xor_sync(0xffffffffu, s2, o2);
        }
        if (tx == 0) {
            g_src[(size_t)row * HH + bn] = s1;
            g_dst[(size_t)row * HH + bn] = s2;
        }
    }
}

// ---------------------------------------------------------------------------
// Kernel 2: fused scores + masked softmax (single-pass) + P@V.
// Mask folded into src/dst (-1e30 => exp -> 0). V tile prefetched into regs
// during score phase. Accumulate uses kk-vectorized LDS.128 + f32x2 FMA.
// ---------------------------------------------------------------------------
__global__ __launch_bounds__(256) void attn_k(const int* __restrict__ adj,
                                              const int* __restrict__ mask) {
    __shared__ float Vt[64][68];
    __shared__ float Pt[64][68];
    __shared__ float dstS[64];
    __shared__ float srcS[64];
    __shared__ float lS[64];

    int it = blockIdx.x, hh = blockIdx.y, b = blockIdx.z;
    int i0 = it * 64;
    int tid = threadIdx.x;
    int ti = tid >> 2, q = tid & 3;        // score mapping: 4 threads/row
    int iy = tid >> 4, ix = tid & 15;      // accumulate mapping: 4x4 tile

    if (tid < 64) {
        int gi = b * NN + i0 + tid;
        float s = g_src[(size_t)gi * HH + hh];
        srcS[tid] = mask[gi] > 0 ? s : NEGBIG;
        lS[tid] = 0.f;
    }
    u64 acc2[4][2] = {};
    const float* hb = g_h + (size_t)(b * NN) * HD + hh * DD;
    const int* adjb = adj + (size_t)(b * NN + i0) * NN;

    // prologue: prefetch tile 0 (V rows + masked dst)
    float4 vr0, vr1, vr2, vr3;
    {
        const float* vp = hb + (size_t)ti * HD + q * 16;
        vr0 = ((const float4*)vp)[0]; vr1 = ((const float4*)vp)[1];
        vr2 = ((const float4*)vp)[2]; vr3 = ((const float4*)vp)[3];
    }
    float dreg = 0.f;
    if (tid < 64) {
        int gj = b * NN + tid;
        float d = g_dst[(size_t)gj * HH + hh];
        dreg = mask[gj] > 0 ? d : NEGBIG;
    }

    for (int t = 0; t < 16; t++) {
        int j0 = t * 64;
        __syncthreads();               // Vt/Pt free (prev accumulate done)
        {
            float* vd = &Vt[ti][q * 16];
            ((float4*)vd)[0] = vr0; ((float4*)vd)[1] = vr1;
            ((float4*)vd)[2] = vr2; ((float4*)vd)[3] = vr3;
        }
        if (tid < 64) dstS[tid] = dreg;
        __syncthreads();

        // --- score: row ti, 16 j's per thread ---
        {
            float si = srcS[ti];
            const float4* dp = (const float4*)&dstS[q * 16];
            float4 dv[4];
            dv[0] = dp[0]; dv[1] = dp[1]; dv[2] = dp[2]; dv[3] = dp[3];
            const int4* arow = (const int4*)(adjb + (size_t)ti * NN + j0 + q * 16);
            float ls = 0.f;
            float* pr = &Pt[ti][q * 16];
#pragma unroll
            for (int k4 = 0; k4 < 4; k4++) {
                int4 a = arow[k4];
                float e0 = si + dv[k4].x; e0 = e0 > 0.f ? e0 : 0.2f * e0;
                float e1 = si + dv[k4].y; e1 = e1 > 0.f ? e1 : 0.2f * e1;
                float e2 = si + dv[k4].z; e2 = e2 > 0.f ? e2 : 0.2f * e2;
                float e3 = si + dv[k4].w; e3 = e3 > 0.f ? e3 : 0.2f * e3;
                float4 p4;
                p4.x = a.x > 0 ? __expf(e0) : 0.f;
                p4.y = a.y > 0 ? __expf(e1) : 0.f;
                p4.z = a.z > 0 ? __expf(e2) : 0.f;
                p4.w = a.w > 0 ? __expf(e3) : 0.f;
                ls += p4.x + p4.y + p4.z + p4.w;
                ((float4*)pr)[k4] = p4;
            }
            ls += __shfl_xor_sync(0xffffffffu, ls, 1);
            ls += __shfl_xor_sync(0xffffffffu, ls, 2);
            if (q == 0) lS[ti] += ls;
        }

        // prefetch next tile's V + dst while scores settle
        if (t < 15) {
            const float* vp = hb + (size_t)(j0 + 64 + ti) * HD + q * 16;
            vr0 = ((const float4*)vp)[0]; vr1 = ((const float4*)vp)[1];
            vr2 = ((const float4*)vp)[2]; vr3 = ((const float4*)vp)[3];
            if (tid < 64) {
                int gj = b * NN + j0 + 64 + tid;
                float d = g_dst[(size_t)gj * HH + hh];
                dreg = mask[gj] > 0 ? d : NEGBIG;
            }
        }
        __syncthreads();               // publish Pt

        // --- accumulate: kk groups of 4, LDS.128-only traffic ---
#pragma unroll 2
        for (int kg = 0; kg < 16; kg++) {
            u64 v00, v01, v10, v11, v20, v21, v30, v31;
            lds_v2u64(v00, v01, &Vt[kg * 4 + 0][ix * 4]);
            lds_v2u64(v10, v11, &Vt[kg * 4 + 1][ix * 4]);
            lds_v2u64(v20, v21, &Vt[kg * 4 + 2][ix * 4]);
            lds_v2u64(v30, v31, &Vt[kg * 4 + 3][ix * 4]);
#pragma unroll
            for (int r = 0; r < 4; r++) {
                float4 p4 = *(const float4*)&Pt[iy * 4 + r][kg * 4];
                u64 p0 = pack2(p4.x), p1 = pack2(p4.y);
                u64 p2 = pack2(p4.z), p3 = pack2(p4.w);
                ffma2(acc2[r][0], p0, v00); ffma2(acc2[r][1], p0, v01);
                ffma2(acc2[r][0], p1, v10); ffma2(acc2[r][1], p1, v11);
                ffma2(acc2[r][0], p2, v20); ffma2(acc2[r][1], p2, v21);
                ffma2(acc2[r][0], p3, v30); ffma2(acc2[r][1], p3, v31);
            }
        }
    }

    // --- epilogue ---
#pragma unroll
    for (int r = 0; r < 4; r++) {
        int row = i0 + iy * 4 + r;
        float l = lS[iy * 4 + r];
        float inv = l > 0.f ? 1.0f / l : 0.f;
        float2 lo = unpack2(acc2[r][0]);
        float2 hi = unpack2(acc2[r][1]);
        float* o = g_att + (size_t)(b * NN + row) * HD + hh * DD + ix * 4;
        *(float4*)o = make_float4(lo.x * inv, lo.y * inv, hi.x * inv, hi.y * inv);
    }
}

// ---------------------------------------------------------------------------
// Kernel 3: LayerNorm. 32 threads/row, 8 floats each, warp-shfl only.
// ---------------------------------------------------------------------------
__global__ __launch_bounds__(256) void ln_k(const int* __restrict__ mask,
                                            const float* __restrict__ gamma,
                                            const float* __restrict__ beta,
                                            float* __restrict__ out) {
    int row = blockIdx.x * 8 + (threadIdx.x >> 5);
    int lane = threadIdx.x & 31;
    float mf = mask[row] > 0 ? 1.f : 0.f;
    const float* ar = g_att + (size_t)row * HD + lane * 8;
    float4 v0 = ((const float4*)ar)[0];
    float4 v1 = ((const float4*)ar)[1];
    v0.x *= mf; v0.y *= mf; v0.z *= mf; v0.w *= mf;
    v1.x *= mf; v1.y *= mf; v1.z *= mf; v1.w *= mf;
    float s = v0.x + v0.y + v0.z + v0.w + v1.x + v1.y + v1.z + v1.w;
    float s2 = v0.x * v0.x + v0.y * v0.y + v0.z * v0.z + v0.w * v0.w
             + v1.x * v1.x + v1.y * v1.y + v1.z * v1.z + v1.w * v1.w;
#pragma unroll
    for (int o = 16; o > 0; o >>= 1) {
        s += __shfl_xor_sync(0xffffffffu, s, o);
        s2 += __shfl_xor_sync(0xffffffffu, s2, o);
    }
    float mu = s * (1.0f / HD);
    float var = s2 * (1.0f / HD) - mu * mu;
    float rstd = rsqrtf(var + EPSV);
    float4 g0 = ((const float4*)(gamma + lane * 8))[0];
    float4 g1 = ((const float4*)(gamma + lane * 8))[1];
    float4 b0 = ((const float4*)(beta + lane * 8))[0];
    float4 b1 = ((const float4*)(beta + lane * 8))[1];
    float* o = out + (size_t)row * HD + lane * 8;
    ((float4*)o)[0] = make_float4((v0.x - mu) * rstd * g0.x + b0.x,
                                  (v0.y - mu) * rstd * g0.y + b0.y,
                                  (v0.z - mu) * rstd * g0.z + b0.z,
                                  (v0.w - mu) * rstd * g0.w + b0.w);
    ((float4*)o)[1] = make_float4((v1.x - mu) * rstd * g1.x + b1.x,
                                  (v1.y - mu) * rstd * g1.y + b1.y,
                                  (v1.z - mu) * rstd * g1.z + b1.z,
                                  (v1.w - mu) * rstd * g1.w + b1.w);
}

// ---------------------------------------------------------------------------
extern "C" void kernel_launch(void* const* d_in, const int* in_sizes, int n_in,
                              void* d_out, int out_size) {
    const float* x = (const float*)d_in[0];
    const int* adj = (const int*)d_in[1];
    const int* mask = (const int*)d_in[2];
    const float* Wm = (const float*)d_in[3];
    const float* a_src = (const float*)d_in[4];
    const float* a_dst = (const float*)d_in[5];
    const float* gamma = (const float*)d_in[6];
    const float* beta = (const float*)d_in[7];
    float* out = (float*)d_out;

    dim3 gg(BB * NN / 64, HD / 64);
    gemm_k<<<gg, 256>>>(x, Wm, a_src, a_dst);
    dim3 ga(NN / 64, HH, BB);
    attn_k<<<ga, 256>>>(adj, mask);
    ln_k<<<BB * NN / 8, 256>>>(mask, gamma, beta, out);
}

// round 8
// speedup vs baseline: 1.3343x; 1.0051x over previous
#include <cuda_runtime.h>
#include <math.h>

#define BB 16
#define NN 1024
#define IND 256
#define HH 4
#define DD 64
#define HD 256
#define EPSV 1e-5f
#define NEGBIG -1.0e30f

typedef unsigned long long u64;

// Scratch (no allocations allowed)
__device__ float g_h[BB * NN * HD];      // projected features [b,n,H*D]
__device__ float g_src[BB * NN * HH];    // src logits [b,n,H]
__device__ float g_dst[BB * NN * HH];    // dst logits [b,n,H]
__device__ float g_att[BB * NN * HD];    // attention output pre-LN

__device__ __forceinline__ void ffma2(u64& d, u64 a, u64 b) {
    asm("fma.rn.f32x2 %0, %1, %2, %0;" : "+l"(d) : "l"(a), "l"(b));
}
__device__ __forceinline__ u64 pack2(float v) {
    u64 r; unsigned u = __float_as_uint(v);
    asm("mov.b64 %0, {%1, %1};" : "=l"(r) : "r"(u));
    return r;
}
__device__ __forceinline__ float2 unpack2(u64 v) {
    unsigned lo, hi;
    asm("mov.b64 {%0, %1}, %2;" : "=r"(lo), "=r"(hi) : "l"(v));
    return make_float2(__uint_as_float(lo), __uint_as_float(hi));
}
__device__ __forceinline__ void lds_v2u64(u64& a, u64& b, const void* p) {
    unsigned addr = (unsigned)__cvta_generic_to_shared(p);
    asm("ld.shared.v2.u64 {%0, %1}, [%2];" : "=l"(a), "=l"(b) : "r"(addr));
}

// ---------------------------------------------------------------------------
// Kernel 1: h = x @ W (M=16384,N=256,K=256). 128x128 block tile, 8x8 thread
// tile, k-slab 8, double-buffered smem, f32x2 FMA. Fused src/dst dots.
// ---------------------------------------------------------------------------
__global__ __launch_bounds__(256) void gemm_k(const float* __restrict__ A,
                                              const float* __restrict__ Wm,
                                              const float* __restrict__ asrc,
                                              const float* __restrict__ adst) {
    __shared__ float As[2][8][132];   // [k][row]
    __shared__ float Bs[2][8][132];   // [k][col]
    int bm = blockIdx.x;              // 128 tiles of 128 rows
    int bn = blockIdx.y;              // 2 tiles of 128 cols (= 2 heads each)
    int tid = threadIdx.x;
    int tx = tid & 15, ty = tid >> 4; // 8x8 tile at (ty*8, tx*8)
    int arow = tid >> 1, acol = (tid & 1) * 4;    // A: 1 float4/thread/slab
    int brow = tid >> 5, bcol = (tid & 31) * 4;   // B: 1 float4/thread/slab
    const float* Ap = A + (size_t)(bm * 128 + arow) * IND;
    const float* Bp = Wm + (size_t)bn * 128;
    u64 acc2[8][4] = {};

    float4 ra = *(const float4*)(Ap + acol);
    float4 rb = *(const float4*)(Bp + (size_t)brow * HD + bcol);
    As[0][acol + 0][arow] = ra.x;
    As[0][acol + 1][arow] = ra.y;
    As[0][acol + 2][arow] = ra.z;
    As[0][acol + 3][arow] = ra.w;
    *(float4*)&Bs[0][brow][bcol] = rb;
    __syncthreads();

    int cur = 0;
    for (int s = 0; s < 32; s++) {
        if (s < 31) {
            ra = *(const float4*)(Ap + (s + 1) * 8 + acol);
            rb = *(const float4*)(Bp + (size_t)((s + 1) * 8 + brow) * HD + bcol);
        }
#pragma unroll
        for (int kk = 0; kk < 8; kk++) {
            u64 b0, b1, b2, b3;
            lds_v2u64(b0, b1, &Bs[cur][kk][tx * 8]);
            lds_v2u64(b2, b3, &Bs[cur][kk][tx * 8 + 4]);
            float4 a0 = *(const float4*)&As[cur][kk][ty * 8];
            float4 a1 = *(const float4*)&As[cur][kk][ty * 8 + 4];
            u64 ap[8];
            ap[0] = pack2(a0.x); ap[1] = pack2(a0.y);
            ap[2] = pack2(a0.z); ap[3] = pack2(a0.w);
            ap[4] = pack2(a1.x); ap[5] = pack2(a1.y);
            ap[6] = pack2(a1.z); ap[7] = pack2(a1.w);
#pragma unroll
            for (int i = 0; i < 8; i++) {
                ffma2(acc2[i][0], ap[i], b0);
                ffma2(acc2[i][1], ap[i], b1);
                ffma2(acc2[i][2], ap[i], b2);
                ffma2(acc2[i][3], ap[i], b3);
            }
        }
        if (s < 31) {
            int nxt = cur ^ 1;
            As[nxt][acol + 0][arow] = ra.x;
            As[nxt][acol + 1][arow] = ra.y;
            As[nxt][acol + 2][arow] = ra.z;
            As[nxt][acol + 3][arow] = ra.w;
            *(float4*)&Bs[nxt][brow][bcol] = rb;
            __syncthreads();
            cur = nxt;
        }
    }

    // epilogue: store h + fused src/dst dots. This thread's 8 cols live in
    // head hd = bn*2 + (tx>>3), local col (tx&7)*8. Row sum needs the 8
    // threads sharing (ty, tx>>3): lanes differ in tx&7 -> xor 1,2,4.
    int hd = bn * 2 + (tx >> 3);
    const float* asp = asrc + hd * DD + (tx & 7) * 8;
    const float* adp = adst + hd * DD + (tx & 7) * 8;
    float4 as0 = ((const float4*)asp)[0], as1 = ((const float4*)asp)[1];
    float4 ad0 = ((const float4*)adp)[0], ad1 = ((const float4*)adp)[1];
#pragma unroll
    for (int i = 0; i < 8; i++) {
        float2 c0 = unpack2(acc2[i][0]);
        float2 c1 = unpack2(acc2[i][1]);
        float2 c2 = unpack2(acc2[i][2]);
        float2 c3 = unpack2(acc2[i][3]);
        int row = bm * 128 + ty * 8 + i;
        float* o = g_h + (size_t)row * HD + bn * 128 + tx * 8;
        ((float4*)o)[0] = make_float4(c0.x, c0.y, c1.x, c1.y);
        ((float4*)o)[1] = make_float4(c2.x, c2.y, c3.x, c3.y);
        float s1 = c0.x * as0.x + c0.y * as0.y + c1.x * as0.z + c1.y * as0.w
                 + c2.x * as1.x + c2.y * as1.y + c3.x * as1.z + c3.y * as1.w;
        float s2 = c0.x * ad0.x + c0.y * ad0.y + c1.x * ad0.z + c1.y * ad0.w
                 + c2.x * ad1.x + c2.y * ad1.y + c3.x * ad1.z + c3.y * ad1.w;
        s1 += __shfl_xor_sync(0xffffffffu, s1, 1);
        s2 += __shfl_xor_sync(0xffffffffu, s2, 1);
        s1 += __shfl_xor_sync(0xffffffffu, s1, 2);
        s2 += __shfl_xor_sync(0xffffffffu, s2, 2);
        s1 += __shfl_xor_sync(0xffffffffu, s1, 4);
        s2 += __shfl_xor_sync(0xffffffffu, s2, 4);
        if ((tx & 7) == 0) {
            g_src[(size_t)row * HH + hd] = s1;
            g_dst[(size_t)row * HH + hd] = s2;
        }
    }
}

// ---------------------------------------------------------------------------
// Kernel 2: fused scores + masked softmax (single-pass) + P@V.
// V tile, dst AND adj all prefetched one tile ahead into registers.
// ---------------------------------------------------------------------------
__global__ __launch_bounds__(256) void attn_k(const int* __restrict__ adj,
                                              const int* __restrict__ mask) {
    __shared__ float Vt[64][68];
    __shared__ float Pt[64][68];
    __shared__ float dstS[64];
    __shared__ float srcS[64];
    __shared__ float lS[64];

    int it = blockIdx.x, hh = blockIdx.y, b = blockIdx.z;
    int i0 = it * 64;
    int tid = threadIdx.x;
    int ti = tid >> 2, q = tid & 3;        // score mapping: 4 threads/row
    int iy = tid >> 4, ix = tid & 15;      // accumulate mapping: 4x4 tile

    if (tid < 64) {
        int gi = b * NN + i0 + tid;
        float s = g_src[(size_t)gi * HH + hh];
        srcS[tid] = mask[gi] > 0 ? s : NEGBIG;
        lS[tid] = 0.f;
    }
    u64 acc2[4][2] = {};
    const float* hb = g_h + (size_t)(b * NN) * HD + hh * DD;
    const int* adjb = adj + (size_t)(b * NN + i0) * NN + (size_t)ti * NN + q * 16;

    // prologue: prefetch tile 0 (V rows, masked dst, adj)
    float4 vr0, vr1, vr2, vr3;
    {
        const float* vp = hb + (size_t)ti * HD + q * 16;
        vr0 = ((const float4*)vp)[0]; vr1 = ((const float4*)vp)[1];
        vr2 = ((const float4*)vp)[2]; vr3 = ((const float4*)vp)[3];
    }
    float dreg = 0.f;
    if (tid < 64) {
        int gj = b * NN + tid;
        float d = g_dst[(size_t)gj * HH + hh];
        dreg = mask[gj] > 0 ? d : NEGBIG;
    }
    int4 aj0, aj1, aj2, aj3;
    {
        const int4* apx = (const int4*)adjb;
        aj0 = apx[0]; aj1 = apx[1]; aj2 = apx[2]; aj3 = apx[3];
    }

    for (int t = 0; t < 16; t++) {
        int j0 = t * 64;
        __syncthreads();               // Vt/Pt free (prev accumulate done)
        {
            float* vd = &Vt[ti][q * 16];
            ((float4*)vd)[0] = vr0; ((float4*)vd)[1] = vr1;
            ((float4*)vd)[2] = vr2; ((float4*)vd)[3] = vr3;
        }
        if (tid < 64) dstS[tid] = dreg;
        __syncthreads();

        // --- score: row ti, 16 j's per thread, adj already in regs ---
        {
            float si = srcS[ti];
            const float4* dp = (const float4*)&dstS[q * 16];
            float4 dv0 = dp[0], dv1 = dp[1], dv2 = dp[2], dv3 = dp[3];
            float ls = 0.f;
            float* pr = &Pt[ti][q * 16];
            float4 p4;
#define SCORE4(AJ, DV, IDX)                                              \
            {                                                            \
                float e0 = si + DV.x; e0 = e0 > 0.f ? e0 : 0.2f * e0;    \
                float e1 = si + DV.y; e1 = e1 > 0.f ? e1 : 0.2f * e1;    \
                float e2 = si + DV.z; e2 = e2 > 0.f ? e2 : 0.2f * e2;    \
                float e3 = si + DV.w; e3 = e3 > 0.f ? e3 : 0.2f * e3;    \
                p4.x = AJ.x > 0 ? __expf(e0) : 0.f;                      \
                p4.y = AJ.y > 0 ? __expf(e1) : 0.f;                      \
                p4.z = AJ.z > 0 ? __expf(e2) : 0.f;                      \
                p4.w = AJ.w > 0 ? __expf(e3) : 0.f;                      \
                ls += p4.x + p4.y + p4.z + p4.w;                         \
                ((float4*)pr)[IDX] = p4;                                 \
            }
            SCORE4(aj0, dv0, 0)
            SCORE4(aj1, dv1, 1)
            SCORE4(aj2, dv2, 2)
            SCORE4(aj3, dv3, 3)
#undef SCORE4
            ls += __shfl_xor_sync(0xffffffffu, ls, 1);
            ls += __shfl_xor_sync(0xffffffffu, ls, 2);
            if (q == 0) lS[ti] += ls;
        }

        // prefetch next tile's V + dst + adj (lands during accumulate)
        if (t < 15) {
            const float* vp = hb + (size_t)(j0 + 64 + ti) * HD + q * 16;
            vr0 = ((const float4*)vp)[0]; vr1 = ((const float4*)vp)[1];
            vr2 = ((const float4*)vp)[2]; vr3 = ((const float4*)vp)[3];
            if (tid < 64) {
                int gj = b * NN + j0 + 64 + tid;
                float d = g_dst[(size_t)gj * HH + hh];
                dreg = mask[gj] > 0 ? d : NEGBIG;
            }
            const int4* apx = (const int4*)(adjb + j0 + 64);
            aj0 = apx[0]; aj1 = apx[1]; aj2 = apx[2]; aj3 = apx[3];
        }
        __syncthreads();               // publish Pt

        // --- accumulate: kk groups of 4, LDS.128-only traffic, f32x2 FMA ---
#pragma unroll 2
        for (int kg = 0; kg < 16; kg++) {
            u64 v00, v01, v10, v11, v20, v21, v30, v31;
            lds_v2u64(v00, v01, &Vt[kg * 4 + 0][ix * 4]);
            lds_v2u64(v10, v11, &Vt[kg * 4 + 1][ix * 4]);
            lds_v2u64(v20, v21, &Vt[kg * 4 + 2][ix * 4]);
            lds_v2u64(v30, v31, &Vt[kg * 4 + 3][ix * 4]);
#pragma unroll
            for (int r = 0; r < 4; r++) {
                float4 p4 = *(const float4*)&Pt[iy * 4 + r][kg * 4];
                u64 p0 = pack2(p4.x), p1 = pack2(p4.y);
                u64 p2 = pack2(p4.z), p3 = pack2(p4.w);
                ffma2(acc2[r][0], p0, v00); ffma2(acc2[r][1], p0, v01);
                ffma2(acc2[r][0], p1, v10); ffma2(acc2[r][1], p1, v11);
                ffma2(acc2[r][0], p2, v20); ffma2(acc2[r][1], p2, v21);
                ffma2(acc2[r][0], p3, v30); ffma2(acc2[r][1], p3, v31);
            }
        }
    }

    // --- epilogue ---
#pragma unroll
    for (int r = 0; r < 4; r++) {
        int row = i0 + iy * 4 + r;
        float l = lS[iy * 4 + r];
        float inv = l > 0.f ? 1.0f / l : 0.f;
        float2 lo = unpack2(acc2[r][0]);
        float2 hi = unpack2(acc2[r][1]);
        float* o = g_att + (size_t)(b * NN + row) * HD + hh * DD + ix * 4;
        *(float4*)o = make_float4(lo.x * inv, lo.y * inv, hi.x * inv, hi.y * inv);
    }
}

// ---------------------------------------------------------------------------
// Kernel 3: LayerNorm. 32 threads/row, 8 floats each, warp-shfl only.
// ---------------------------------------------------------------------------
__global__ __launch_bounds__(256) void ln_k(const int* __restrict__ mask,
                                            const float* __restrict__ gamma,
                                            const float* __restrict__ beta,
                                            float* __restrict__ out) {
    int row = blockIdx.x * 8 + (threadIdx.x >> 5);
    int lane = threadIdx.x & 31;
    float mf = mask[row] > 0 ? 1.f : 0.f;
    const float* ar = g_att + (size_t)row * HD + lane * 8;
    float4 v0 = ((const float4*)ar)[0];
    float4 v1 = ((const float4*)ar)[1];
    v0.x *= mf; v0.y *= mf; v0.z *= mf; v0.w *= mf;
    v1.x *= mf; v1.y *= mf; v1.z *= mf; v1.w *= mf;
    float s = v0.x + v0.y + v0.z + v0.w + v1.x + v1.y + v1.z + v1.w;
    float s2 = v0.x * v0.x + v0.y * v0.y + v0.z * v0.z + v0.w * v0.w
             + v1.x * v1.x + v1.y * v1.y + v1.z * v1.z + v1.w * v1.w;
#pragma unroll
    for (int o = 16; o > 0; o >>= 1) {
        s += __shfl_xor_sync(0xffffffffu, s, o);
        s2 += __shfl_xor_sync(0xffffffffu, s2, o);
    }
    float mu = s * (1.0f / HD);
    float var = s2 * (1.0f / HD) - mu * mu;
    float rstd = rsqrtf(var + EPSV);
    float4 g0 = ((const float4*)(gamma + lane * 8))[0];
    float4 g1 = ((const float4*)(gamma + lane * 8))[1];
    float4 b0 = ((const float4*)(beta + lane * 8))[0];
    float4 b1 = ((const float4*)(beta + lane * 8))[1];
    float* o = out + (size_t)row * HD + lane * 8;
    ((float4*)o)[0] = make_float4((v0.x - mu) * rstd * g0.x + b0.x,
                                  (v0.y - mu) * rstd * g0.y + b0.y,
                                  (v0.z - mu) * rstd * g0.z + b0.z,
                                  (v0.w - mu) * rstd * g0.w + b0.w);
    ((float4*)o)[1] = make_float4((v1.x - mu) * rstd * g1.x + b1.x,
                                  (v1.y - mu) * rstd * g1.y + b1.y,
                                  (v1.z - mu) * rstd * g1.z + b1.z,
                                  (v1.w - mu) * rstd * g1.w + b1.w);
}

// ---------------------------------------------------------------------------
extern "C" void kernel_launch(void* const* d_in, const int* in_sizes, int n_in,
                              void* d_out, int out_size) {
    const float* x = (const float*)d_in[0];
    const int* adj = (const int*)d_in[1];
    const int* mask = (const int*)d_in[2];
    const float* Wm = (const float*)d_in[3];
    const float* a_src = (const float*)d_in[4];
    const float* a_dst = (const float*)d_in[5];
    const float* gamma = (const float*)d_in[6];
    const float* beta = (const float*)d_in[7];
    float* out = (float*)d_out;

    dim3 gg(BB * NN / 128, HD / 128);
    gemm_k<<<gg, 256>>>(x, Wm, a_src, a_dst);
    dim3 ga(NN / 64, HH, BB);
    attn_k<<<ga, 256>>>(adj, mask);
    ln_k<<<BB * NN / 8, 256>>>(mask, gamma, beta, out);
}

// round 10
// speedup vs baseline: 2.0837x; 1.5616x over previous
#include <cuda_runtime.h>
#include <math.h>
#include <stdint.h>

#define BB 16
#define NN 1024
#define IND 256
#define HH 4
#define DD 64
#define HD 256
#define EPSV 1e-5f
#define NEGBIG -1.0e30f

typedef unsigned long long u64;
typedef unsigned int u32;

// Scratch (no allocations allowed)
__device__ unsigned short g_hbhi[BB * NN * HD];  // h high bf16 plane
__device__ unsigned short g_hblo[BB * NN * HD];  // h low  bf16 plane
__device__ float g_src[BB * NN * HH];
__device__ float g_dst[BB * NN * HH];
__device__ float g_att[BB * NN * HD];

// ---------------- f32x2 helpers (gemm) ----------------
__device__ __forceinline__ void ffma2(u64& d, u64 a, u64 b) {
    asm("fma.rn.f32x2 %0, %1, %2, %0;" : "+l"(d) : "l"(a), "l"(b));
}
__device__ __forceinline__ u64 pack2(float v) {
    u64 r; u32 u = __float_as_uint(v);
    asm("mov.b64 %0, {%1, %1};" : "=l"(r) : "r"(u));
    return r;
}
__device__ __forceinline__ float2 unpack2(u64 v) {
    u32 lo, hi;
    asm("mov.b64 {%0, %1}, %2;" : "=r"(lo), "=r"(hi) : "l"(v));
    return make_float2(__uint_as_float(lo), __uint_as_float(hi));
}
__device__ __forceinline__ void lds_v2u64(u64& a, u64& b, const void* p) {
    u32 addr = (u32)__cvta_generic_to_shared(p);
    asm("ld.shared.v2.u64 {%0, %1}, [%2];" : "=l"(a), "=l"(b) : "r"(addr));
}

// ---------------- bf16 split helpers ----------------
__device__ __forceinline__ float bhi(float x) {
    return __uint_as_float(__float_as_uint(x) & 0xffff0000u);
}
// pack (even, odd) -> bf16x2 (even element in low half)
__device__ __forceinline__ u32 cvt2(float e, float o) {
    u32 r;
    asm("cvt.rn.bf16x2.f32 %0, %1, %2;" : "=r"(r) : "f"(o), "f"(e));
    return r;
}

// ---------------- mma.sync / ldmatrix helpers (sm_80+ baseline PTX) --------
__device__ __forceinline__ u32 smem_u32(const void* p) {
    return (u32)__cvta_generic_to_shared(p);
}
__device__ __forceinline__ void ldsm_x4(u32* r, u32 addr) {
    asm volatile("ldmatrix.sync.aligned.m8n8.x4.shared.b16 {%0,%1,%2,%3}, [%4];"
                 : "=r"(r[0]), "=r"(r[1]), "=r"(r[2]), "=r"(r[3]) : "r"(addr));
}
__device__ __forceinline__ void ldsm_x4t(u32* r, u32 addr) {
    asm volatile("ldmatrix.sync.aligned.m8n8.x4.trans.shared.b16 {%0,%1,%2,%3}, [%4];"
                 : "=r"(r[0]), "=r"(r[1]), "=r"(r[2]), "=r"(r[3]) : "r"(addr));
}
__device__ __forceinline__ void mma16816(float* c, const u32* a, u32 b0, u32 b1) {
    asm volatile(
        "mma.sync.aligned.m16n8k16.row.col.f32.bf16.bf16.f32 "
        "{%0,%1,%2,%3}, {%4,%5,%6,%7}, {%8,%9}, {%0,%1,%2,%3};"
        : "+f"(c[0]), "+f"(c[1]), "+f"(c[2]), "+f"(c[3])
        : "r"(a[0]), "r"(a[1]), "r"(a[2]), "r"(a[3]), "r"(b0), "r"(b1));
}

// ---------------------------------------------------------------------------
// Kernel 1: h = x @ W. 128x128 tile, 8x8/thread, f32x2 FMA, double-buffered.
// Epilogue: bf16 hi/lo planes of h + fused src/dst head dot products.
// ---------------------------------------------------------------------------
__global__ __launch_bounds__(256) void gemm_k(const float* __restrict__ A,
                                              const float* __restrict__ Wm,
                                              const float* __restrict__ asrc,
                                              const float* __restrict__ adst) {
    __shared__ float As[2][8][132];
    __shared__ float Bs[2][8][132];
    int bm = blockIdx.x, bn = blockIdx.y;
    int tid = threadIdx.x;
    int tx = tid & 15, ty = tid >> 4;
    int arow = tid >> 1, acol = (tid & 1) * 4;
    int brow = tid >> 5, bcol = (tid & 31) * 4;
    const float* Ap = A + (size_t)(bm * 128 + arow) * IND;
    const float* Bp = Wm + (size_t)bn * 128;
    u64 acc2[8][4] = {};

    float4 ra = *(const float4*)(Ap + acol);
    float4 rb = *(const float4*)(Bp + (size_t)brow * HD + bcol);
    As[0][acol + 0][arow] = ra.x;
    As[0][acol + 1][arow] = ra.y;
    As[0][acol + 2][arow] = ra.z;
    As[0][acol + 3][arow] = ra.w;
    *(float4*)&Bs[0][brow][bcol] = rb;
    __syncthreads();

    int cur = 0;
    for (int s = 0; s < 32; s++) {
        if (s < 31) {
            ra = *(const float4*)(Ap + (s + 1) * 8 + acol);
            rb = *(const float4*)(Bp + (size_t)((s + 1) * 8 + brow) * HD + bcol);
        }
#pragma unroll
        for (int kk = 0; kk < 8; kk++) {
            u64 b0, b1, b2, b3;
            lds_v2u64(b0, b1, &Bs[cur][kk][tx * 8]);
            lds_v2u64(b2, b3, &Bs[cur][kk][tx * 8 + 4]);
            float4 a0 = *(const float4*)&As[cur][kk][ty * 8];
            float4 a1 = *(const float4*)&As[cur][kk][ty * 8 + 4];
            u64 ap[8];
            ap[0] = pack2(a0.x); ap[1] = pack2(a0.y);
            ap[2] = pack2(a0.z); ap[3] = pack2(a0.w);
            ap[4] = pack2(a1.x); ap[5] = pack2(a1.y);
            ap[6] = pack2(a1.z); ap[7] = pack2(a1.w);
#pragma unroll
            for (int i = 0; i < 8; i++) {
                ffma2(acc2[i][0], ap[i], b0);
                ffma2(acc2[i][1], ap[i], b1);
                ffma2(acc2[i][2], ap[i], b2);
                ffma2(acc2[i][3], ap[i], b3);
            }
        }
        if (s < 31) {
            int nxt = cur ^ 1;
            As[nxt][acol + 0][arow] = ra.x;
            As[nxt][acol + 1][arow] = ra.y;
            As[nxt][acol + 2][arow] = ra.z;
            As[nxt][acol + 3][arow] = ra.w;
            *(float4*)&Bs[nxt][brow][bcol] = rb;
            __syncthreads();
            cur = nxt;
        }
    }

    int hd = bn * 2 + (tx >> 3);
    const float* asp = asrc + hd * DD + (tx & 7) * 8;
    const float* adp = adst + hd * DD + (tx & 7) * 8;
    float4 as0 = ((const float4*)asp)[0], as1 = ((const float4*)asp)[1];
    float4 ad0 = ((const float4*)adp)[0], ad1 = ((const float4*)adp)[1];
#pragma unroll
    for (int i = 0; i < 8; i++) {
        float2 c0 = unpack2(acc2[i][0]);
        float2 c1 = unpack2(acc2[i][1]);
        float2 c2 = unpack2(acc2[i][2]);
        float2 c3 = unpack2(acc2[i][3]);
        int row = bm * 128 + ty * 8 + i;
        float v[8] = {c0.x, c0.y, c1.x, c1.y, c2.x, c2.y, c3.x, c3.y};
        float h[8], l[8];
#pragma unroll
        for (int k = 0; k < 8; k++) { h[k] = bhi(v[k]); l[k] = v[k] - h[k]; }
        uint4 HV = make_uint4(cvt2(h[0], h[1]), cvt2(h[2], h[3]),
                              cvt2(h[4], h[5]), cvt2(h[6], h[7]));
        uint4 LV = make_uint4(cvt2(l[0], l[1]), cvt2(l[2], l[3]),
                              cvt2(l[4], l[5]), cvt2(l[6], l[7]));
        size_t off = (size_t)row * HD + bn * 128 + tx * 8;
        *(uint4*)(g_hbhi + off) = HV;
        *(uint4*)(g_hblo + off) = LV;
        float s1 = v[0] * as0.x + v[1] * as0.y + v[2] * as0.z + v[3] * as0.w
                 + v[4] * as1.x + v[5] * as1.y + v[6] * as1.z + v[7] * as1.w;
        float s2 = v[0] * ad0.x + v[1] * ad0.y + v[2] * ad0.z + v[3] * ad0.w
                 + v[4] * ad1.x + v[5] * ad1.y + v[6] * ad1.z + v[7] * ad1.w;
        s1 += __shfl_xor_sync(0xffffffffu, s1, 1);
        s2 += __shfl_xor_sync(0xffffffffu, s2, 1);
        s1 += __shfl_xor_sync(0xffffffffu, s1, 2);
        s2 += __shfl_xor_sync(0xffffffffu, s2, 2);
        s1 += __shfl_xor_sync(0xffffffffu, s1, 4);
        s2 += __shfl_xor_sync(0xffffffffu, s2, 4);
        if ((tx & 7) == 0) {
            g_src[(size_t)row * HH + hd] = s1;
            g_dst[(size_t)row * HH + hd] = s2;
        }
    }
}

// ---------------------------------------------------------------------------
// Kernel 2: attention via mma.sync bf16 (split hi/lo, 3 passes).
// Block = (64 i-rows, head, batch), 256 threads / 8 warps.
// Warp (wid&3) -> 16-row m block; (wid>>2) -> 32-col d block.
// ---------------------------------------------------------------------------
__global__ __launch_bounds__(256) void attn_k(const int* __restrict__ adj,
                                              const int* __restrict__ mask) {
    __shared__ __align__(16) unsigned short Phi[64][72];
    __shared__ __align__(16) unsigned short Plo[64][72];
    __shared__ __align__(16) unsigned short Vhi[64][72];
    __shared__ __align__(16) unsigned short Vlo[64][72];
    __shared__ float s_dst[64];
    __shared__ float s_l[64];

    int it = blockIdx.x, hh = blockIdx.y, b = blockIdx.z;
    int i0 = it * 64;
    int tid = threadIdx.x;
    int lane = tid & 31, wid = tid >> 5;
    int ti = tid >> 2, q = tid & 3;      // 4 threads per row, 16 j each

    int gi = b * NN + i0 + ti;
    float srcv = mask[gi] > 0 ? g_src[(size_t)gi * HH + hh] : NEGBIG;
    const int* arow = adj + (size_t)gi * NN + q * 16;
    float lsum = 0.f;

    float c[4][4] = {};                  // fp32 accum fragments (4 n-blocks)
    int m0 = (wid & 3) * 16, n0 = (wid >> 2) * 32;
    int lr = lane & 15, lc = (lane >> 4) * 8;

    // prefetch tile 0: adj, V hi/lo, dst
    int4 aj0, aj1, aj2, aj3;
    uint4 vh0, vh1, vl0, vl1;
    float dv = 0.f;
    {
        const int4* ap = (const int4*)arow;
        aj0 = ap[0]; aj1 = ap[1]; aj2 = ap[2]; aj3 = ap[3];
        const uint4* hp = (const uint4*)(g_hbhi + (size_t)(b * NN + ti) * HD + hh * 64 + q * 16);
        const uint4* lp = (const uint4*)(g_hblo + (size_t)(b * NN + ti) * HD + hh * 64 + q * 16);
        vh0 = hp[0]; vh1 = hp[1];
        vl0 = lp[0]; vl1 = lp[1];
        if (tid < 64) {
            int gj = b * NN + tid;
            float d = g_dst[(size_t)gj * HH + hh];
            dv = mask[gj] > 0 ? d : NEGBIG;
        }
    }

    for (int t = 0; t < 16; t++) {
        __syncthreads();                  // prev mma done; smem writable
        *(uint4*)&Vhi[ti][q * 16] = vh0;
        *(uint4*)&Vhi[ti][q * 16 + 8] = vh1;
        *(uint4*)&Vlo[ti][q * 16] = vl0;
        *(uint4*)&Vlo[ti][q * 16 + 8] = vl1;
        if (tid < 64) s_dst[tid] = dv;
        __syncthreads();

        // --- scores: p = valid ? exp(leaky(src+dst)) : 0 ; split -> Phi/Plo
        {
            const float4* dp = (const float4*)&s_dst[q * 16];
            float4 d0 = dp[0], d1 = dp[1], d2 = dp[2], d3 = dp[3];
            float p[16];
            float e;
#define SC4(AJ, DV, K)                                                        \
            e = srcv + DV.x; e = fmaxf(e, 0.2f * e); p[K+0] = AJ.x > 0 ? __expf(e) : 0.f; \
            e = srcv + DV.y; e = fmaxf(e, 0.2f * e); p[K+1] = AJ.y > 0 ? __expf(e) : 0.f; \
            e = srcv + DV.z; e = fmaxf(e, 0.2f * e); p[K+2] = AJ.z > 0 ? __expf(e) : 0.f; \
            e = srcv + DV.w; e = fmaxf(e, 0.2f * e); p[K+3] = AJ.w > 0 ? __expf(e) : 0.f;
            SC4(aj0, d0, 0) SC4(aj1, d1, 4) SC4(aj2, d2, 8) SC4(aj3, d3, 12)
#undef SC4
#pragma unroll
            for (int k = 0; k < 16; k++) lsum += p[k];
            u32 hw[8], lw[8];
#pragma unroll
            for (int g = 0; g < 8; g++) {
                float h0 = bhi(p[2 * g]), h1 = bhi(p[2 * g + 1]);
                hw[g] = cvt2(h0, h1);
                lw[g] = cvt2(p[2 * g] - h0, p[2 * g + 1] - h1);
            }
            *(uint4*)&Phi[ti][q * 16] = make_uint4(hw[0], hw[1], hw[2], hw[3]);
            *(uint4*)&Phi[ti][q * 16 + 8] = make_uint4(hw[4], hw[5], hw[6], hw[7]);
            *(uint4*)&Plo[ti][q * 16] = make_uint4(lw[0], lw[1], lw[2], lw[3]);
            *(uint4*)&Plo[ti][q * 16 + 8] = make_uint4(lw[4], lw[5], lw[6], lw[7]);
        }

        // prefetch next tile (lands during mma)
        if (t < 15) {
            int j0n = (t + 1) * 64;
            const int4* ap = (const int4*)(arow + j0n);
            aj0 = ap[0]; aj1 = ap[1]; aj2 = ap[2]; aj3 = ap[3];
            const uint4* hp = (const uint4*)(g_hbhi + (size_t)(b * NN + j0n + ti) * HD + hh * 64 + q * 16);
            const uint4* lp = (const uint4*)(g_hblo + (size_t)(b * NN + j0n + ti) * HD + hh * 64 + q * 16);
            vh0 = hp[0]; vh1 = hp[1];
            vl0 = lp[0]; vl1 = lp[1];
            if (tid < 64) {
                int gj = b * NN + j0n + tid;
                float d = g_dst[(size_t)gj * HH + hh];
                dv = mask[gj] > 0 ? d : NEGBIG;
            }
        }
        __syncthreads();                  // P + V visible

        // --- mma: 4 k-steps of 16, 3 passes (hi.hi, lo.hi, hi.lo) ---
#pragma unroll
        for (int ks = 0; ks < 4; ks++) {
            u32 ahi[4], alo[4], bh[8], bl[8];
            ldsm_x4(ahi, smem_u32(&Phi[m0 + lr][ks * 16 + lc]));
            ldsm_x4(alo, smem_u32(&Plo[m0 + lr][ks * 16 + lc]));
            int br = ks * 16 + lr;
            ldsm_x4t(bh,     smem_u32(&Vhi[br][n0 + lc]));
            ldsm_x4t(bh + 4, smem_u32(&Vhi[br][n0 + 16 + lc]));
            ldsm_x4t(bl,     smem_u32(&Vlo[br][n0 + lc]));
            ldsm_x4t(bl + 4, smem_u32(&Vlo[br][n0 + 16 + lc]));
#pragma unroll
            for (int nb = 0; nb < 4; nb++) {
                mma16816(c[nb], ahi, bh[2 * nb], bh[2 * nb + 1]);
                mma16816(c[nb], alo, bh[2 * nb], bh[2 * nb + 1]);
                mma16816(c[nb], ahi, bl[2 * nb], bl[2 * nb + 1]);
            }
        }
    }

    // --- final l reduction + epilogue ---
    lsum += __shfl_xor_sync(0xffffffffu, lsum, 1);
    lsum += __shfl_xor_sync(0xffffffffu, lsum, 2);
    if (q == 0) s_l[ti] = lsum;
    __syncthreads();
    {
        int r0 = lane >> 2, col0 = (lane & 3) * 2;
        float l0 = s_l[m0 + r0], l1 = s_l[m0 + r0 + 8];
        float inv0 = l0 > 0.f ? 1.0f / l0 : 0.f;
        float inv1 = l1 > 0.f ? 1.0f / l1 : 0.f;
        float* ob = g_att + (size_t)(b * NN + i0 + m0 + r0) * HD + hh * 64 + n0 + col0;
#pragma unroll
        for (int nb = 0; nb < 4; nb++) {
            *(float2*)(ob + nb * 8) = make_float2(c[nb][0] * inv0, c[nb][1] * inv0);
            *(float2*)(ob + 8 * HD + nb * 8) = make_float2(c[nb][2] * inv1, c[nb][3] * inv1);
        }
    }
}

// ---------------------------------------------------------------------------
// Kernel 3: LayerNorm. 32 threads/row, warp-shfl only.
// ---------------------------------------------------------------------------
__global__ __launch_bounds__(256) void ln_k(const int* __restrict__ mask,
                                            const float* __restrict__ gamma,
                                            const float* __restrict__ beta,
                                            float* __restrict__ out) {
    int row = blockIdx.x * 8 + (threadIdx.x >> 5);
    int lane = threadIdx.x & 31;
    float mf = mask[row] > 0 ? 1.f : 0.f;
    const float* ar = g_att + (size_t)row * HD + lane * 8;
    float4 v0 = ((const float4*)ar)[0];
    float4 v1 = ((const float4*)ar)[1];
    v0.x *= mf; v0.y *= mf; v0.z *= mf; v0.w *= mf;
    v1.x *= mf; v1.y *= mf; v1.z *= mf; v1.w *= mf;
    float s = v0.x + v0.y + v0.z + v0.w + v1.x + v1.y + v1.z + v1.w;
    float s2 = v0.x * v0.x + v0.y * v0.y + v0.z * v0.z + v0.w * v0.w
             + v1.x * v1.x + v1.y * v1.y + v1.z * v1.z + v1.w * v1.w;
#pragma unroll
    for (int o = 16; o > 0; o >>= 1) {
        s += __shfl_xor_sync(0xffffffffu, s, o);
        s2 += __shfl_xor_sync(0xffffffffu, s2, o);
    }
    float mu = s * (1.0f / HD);
    float var = s2 * (1.0f / HD) - mu * mu;
    float rstd = rsqrtf(var + EPSV);
    float4 g0 = ((const float4*)(gamma + lane * 8))[0];
    float4 g1 = ((const float4*)(gamma + lane * 8))[1];
    float4 b0 = ((const float4*)(beta + lane * 8))[0];
    float4 b1 = ((const float4*)(beta + lane * 8))[1];
    float* o = out + (size_t)row * HD + lane * 8;
    ((float4*)o)[0] = make_float4((v0.x - mu) * rstd * g0.x + b0.x,
                                  (v0.y - mu) * rstd * g0.y + b0.y,
                                  (v0.z - mu) * rstd * g0.z + b0.z,
                                  (v0.w - mu) * rstd * g0.w + b0.w);
    ((float4*)o)[1] = make_float4((v1.x - mu) * rstd * g1.x + b1.x,
                                  (v1.y - mu) * rstd * g1.y + b1.y,
                                  (v1.z - mu) * rstd * g1.z + b1.z,
                                  (v1.w - mu) * rstd * g1.w + b1.w);
}

// ---------------------------------------------------------------------------
extern "C" void kernel_launch(void* const* d_in, const int* in_sizes, int n_in,
                              void* d_out, int out_size) {
    const float* x = (const float*)d_in[0];
    const int* adj = (const int*)d_in[1];
    const int* mask = (const int*)d_in[2];
    const float* Wm = (const float*)d_in[3];
    const float* a_src = (const float*)d_in[4];
    const float* a_dst = (const float*)d_in[5];
    const float* gamma = (const float*)d_in[6];
    const float* beta = (const float*)d_in[7];
    float* out = (float*)d_out;

    dim3 gg(BB * NN / 128, HD / 128);
    gemm_k<<<gg, 256>>>(x, Wm, a_src, a_dst);
    dim3 ga(NN / 64, HH, BB);
    attn_k<<<ga, 256>>>(adj, mask);
    ln_k<<<BB * NN / 8, 256>>>(mask, gamma, beta, out);
}

// round 11
// speedup vs baseline: 2.3423x; 1.1241x over previous
#include <cuda_runtime.h>
#include <math.h>
#include <stdint.h>

#define BB 16
#define NN 1024
#define IND 256
#define HH 4
#define DD 64
#define HD 256
#define EPSV 1e-5f
#define NEGBIG -1.0e30f

typedef unsigned long long u64;
typedef unsigned int u32;
typedef unsigned short u16;

// Scratch (no allocations allowed)
__device__ u16 g_hbhi[BB * NN * HD];  // h high bf16 plane
__device__ u16 g_hblo[BB * NN * HD];  // h low  bf16 plane
__device__ float g_src[BB * NN * HH];
__device__ float g_dst[BB * NN * HH];
__device__ float g_att[BB * NN * HD];

// ---------------- bf16 split helpers ----------------
__device__ __forceinline__ float bhi(float x) {
    return __uint_as_float(__float_as_uint(x) & 0xffff0000u);
}
// pack (even, odd) -> bf16x2 (even element in low half)
__device__ __forceinline__ u32 cvt2(float e, float o) {
    u32 r;
    asm("cvt.rn.bf16x2.f32 %0, %1, %2;" : "=r"(r) : "f"(o), "f"(e));
    return r;
}

// ---------------- mma.sync / ldmatrix helpers (sm_80+ baseline PTX) --------
__device__ __forceinline__ u32 smem_u32(const void* p) {
    return (u32)__cvta_generic_to_shared(p);
}
__device__ __forceinline__ void ldsm_x4(u32* r, u32 addr) {
    asm volatile("ldmatrix.sync.aligned.m8n8.x4.shared.b16 {%0,%1,%2,%3}, [%4];"
                 : "=r"(r[0]), "=r"(r[1]), "=r"(r[2]), "=r"(r[3]) : "r"(addr));
}
__device__ __forceinline__ void ldsm_x4t(u32* r, u32 addr) {
    asm volatile("ldmatrix.sync.aligned.m8n8.x4.trans.shared.b16 {%0,%1,%2,%3}, [%4];"
                 : "=r"(r[0]), "=r"(r[1]), "=r"(r[2]), "=r"(r[3]) : "r"(addr));
}
__device__ __forceinline__ void mma16816(float* c, const u32* a, u32 b0, u32 b1) {
    asm volatile(
        "mma.sync.aligned.m16n8k16.row.col.f32.bf16.bf16.f32 "
        "{%0,%1,%2,%3}, {%4,%5,%6,%7}, {%8,%9}, {%0,%1,%2,%3};"
        : "+f"(c[0]), "+f"(c[1]), "+f"(c[2]), "+f"(c[3])
        : "r"(a[0]), "r"(a[1]), "r"(a[2]), "r"(a[3]), "r"(b0), "r"(b1));
}

// ---------------------------------------------------------------------------
// Kernel 1: h = x @ W via split-bf16 mma.sync (3 passes: hh + lh + hl).
// Block = 128 rows x 128 cols (2 heads), 256 threads / 8 warps.
// Warp wid owns m-block wid*16, all 128 cols (16 n-blocks of 8).
// k-slabs of 16; x and W converted to bf16 hi/lo planes while staging.
// Epilogue: h hi/lo planes + fused src/dst head dot products.
// ---------------------------------------------------------------------------
__global__ __launch_bounds__(256) void gemm_k(const float* __restrict__ A,
                                              const float* __restrict__ Wm,
                                              const float* __restrict__ asrc,
                                              const float* __restrict__ adst) {
    __shared__ __align__(16) u16 Xhi[128][24];   // [row][k] (+pad)
    __shared__ __align__(16) u16 Xlo[128][24];
    __shared__ __align__(16) u16 Whi[16][136];   // [k][n] (+pad)
    __shared__ __align__(16) u16 Wlo[16][136];

    int bm = blockIdx.x, bn = blockIdx.y;
    int tid = threadIdx.x;
    int lane = tid & 31, wid = tid >> 5;
    int xr = tid >> 1, xc = (tid & 1) * 8;   // x stage: row, 8 k-cols
    int wr = tid >> 4, wc = (tid & 15) * 8;  // W stage: k-row, 8 n-cols
    const float* Ap = A + (size_t)(bm * 128 + xr) * IND + xc;
    const float* Bp = Wm + (size_t)wr * HD + bn * 128 + wc;

    float c[16][4] = {};
    int m0 = wid * 16;
    int lr = lane & 15, lc = (lane >> 4) * 8;

    // prologue: load slab 0 into regs
    float4 xa = ((const float4*)Ap)[0], xb = ((const float4*)Ap)[1];
    float4 wa = ((const float4*)Bp)[0], wb = ((const float4*)Bp)[1];

    for (int s = 0; s < 16; s++) {
        // stage current slab: convert fp32 -> bf16 hi/lo, write smem
        {
            float v[8] = {xa.x, xa.y, xa.z, xa.w, xb.x, xb.y, xb.z, xb.w};
            u32 hw[4], lw[4];
#pragma unroll
            for (int g = 0; g < 4; g++) {
                float h0 = bhi(v[2 * g]), h1 = bhi(v[2 * g + 1]);
                hw[g] = cvt2(h0, h1);
                lw[g] = cvt2(v[2 * g] - h0, v[2 * g + 1] - h1);
            }
            *(uint4*)&Xhi[xr][xc] = make_uint4(hw[0], hw[1], hw[2], hw[3]);
            *(uint4*)&Xlo[xr][xc] = make_uint4(lw[0], lw[1], lw[2], lw[3]);
            float w[8] = {wa.x, wa.y, wa.z, wa.w, wb.x, wb.y, wb.z, wb.w};
#pragma unroll
            for (int g = 0; g < 4; g++) {
                float h0 = bhi(w[2 * g]), h1 = bhi(w[2 * g + 1]);
                hw[g] = cvt2(h0, h1);
                lw[g] = cvt2(w[2 * g] - h0, w[2 * g + 1] - h1);
            }
            *(uint4*)&Whi[wr][wc] = make_uint4(hw[0], hw[1], hw[2], hw[3]);
            *(uint4*)&Wlo[wr][wc] = make_uint4(lw[0], lw[1], lw[2], lw[3]);
        }
        __syncthreads();
        // prefetch next slab (lands during mma)
        if (s < 15) {
            xa = ((const float4*)(Ap + (s + 1) * 16))[0];
            xb = ((const float4*)(Ap + (s + 1) * 16))[1];
            wa = ((const float4*)(Bp + (size_t)(s + 1) * 16 * HD))[0];
            wb = ((const float4*)(Bp + (size_t)(s + 1) * 16 * HD))[1];
        }
        // mma on staged slab
        u32 ahi[4], alo[4];
        ldsm_x4(ahi, smem_u32(&Xhi[m0 + lr][lc]));
        ldsm_x4(alo, smem_u32(&Xlo[m0 + lr][lc]));
#pragma unroll
        for (int half = 0; half < 2; half++) {
            u32 bh[16], bl[16];
#pragma unroll
            for (int g = 0; g < 4; g++) {
                ldsm_x4t(bh + 4 * g, smem_u32(&Whi[lr][half * 64 + g * 16 + lc]));
                ldsm_x4t(bl + 4 * g, smem_u32(&Wlo[lr][half * 64 + g * 16 + lc]));
            }
#pragma unroll
            for (int n2 = 0; n2 < 8; n2++) {
                int nb = half * 8 + n2;
                mma16816(c[nb], ahi, bh[2 * n2], bh[2 * n2 + 1]);
                mma16816(c[nb], alo, bh[2 * n2], bh[2 * n2 + 1]);
                mma16816(c[nb], ahi, bl[2 * n2], bl[2 * n2 + 1]);
            }
        }
        __syncthreads();
    }

    // --- epilogue: h planes + src/dst dots from fragments ---
    int r0 = lane >> 2, col0 = (lane & 3) * 2;
    int row0 = bm * 128 + m0 + r0;
    int row1 = row0 + 8;
    float ps[2][2] = {}, pd[2][2] = {};   // [row][head-local]
#pragma unroll
    for (int nb = 0; nb < 16; nb++) {
        int hdl = nb >> 3;
        int cloc = (nb & 7) * 8 + col0;
        int hd = bn * 2 + hdl;
        float as0 = asrc[hd * DD + cloc], as1 = asrc[hd * DD + cloc + 1];
        float ad0 = adst[hd * DD + cloc], ad1 = adst[hd * DD + cloc + 1];
        float v0 = c[nb][0], v1 = c[nb][1], v2 = c[nb][2], v3 = c[nb][3];
        ps[0][hdl] += v0 * as0 + v1 * as1;
        ps[1][hdl] += v2 * as0 + v3 * as1;
        pd[0][hdl] += v0 * ad0 + v1 * ad1;
        pd[1][hdl] += v2 * ad0 + v3 * ad1;
        int gcol = bn * 128 + nb * 8 + col0;
        float h0 = bhi(v0), h1 = bhi(v1);
        *(u32*)&g_hbhi[(size_t)row0 * HD + gcol] = cvt2(h0, h1);
        *(u32*)&g_hblo[(size_t)row0 * HD + gcol] = cvt2(v0 - h0, v1 - h1);
        float h2 = bhi(v2), h3 = bhi(v3);
        *(u32*)&g_hbhi[(size_t)row1 * HD + gcol] = cvt2(h2, h3);
        *(u32*)&g_hblo[(size_t)row1 * HD + gcol] = cvt2(v2 - h2, v3 - h3);
    }
#pragma unroll
    for (int r = 0; r < 2; r++)
#pragma unroll
        for (int h = 0; h < 2; h++) {
            ps[r][h] += __shfl_xor_sync(0xffffffffu, ps[r][h], 1);
            ps[r][h] += __shfl_xor_sync(0xffffffffu, ps[r][h], 2);
            pd[r][h] += __shfl_xor_sync(0xffffffffu, pd[r][h], 1);
            pd[r][h] += __shfl_xor_sync(0xffffffffu, pd[r][h], 2);
        }
    if ((lane & 3) == 0) {
#pragma unroll
        for (int h = 0; h < 2; h++) {
            g_src[(size_t)row0 * HH + bn * 2 + h] = ps[0][h];
            g_src[(size_t)row1 * HH + bn * 2 + h] = ps[1][h];
            g_dst[(size_t)row0 * HH + bn * 2 + h] = pd[0][h];
            g_dst[(size_t)row1 * HH + bn * 2 + h] = pd[1][h];
        }
    }
}

// ---------------------------------------------------------------------------
// Kernel 2: attention via mma.sync bf16 (split hi/lo, 3 passes).
// Block = (64 i-rows, head, batch), 256 threads / 8 warps.  (R10, unchanged)
// ---------------------------------------------------------------------------
__global__ __launch_bounds__(256) void attn_k(const int* __restrict__ adj,
                                              const int* __restrict__ mask) {
    __shared__ __align__(16) u16 Phi[64][72];
    __shared__ __align__(16) u16 Plo[64][72];
    __shared__ __align__(16) u16 Vhi[64][72];
    __shared__ __align__(16) u16 Vlo[64][72];
    __shared__ float s_dst[64];
    __shared__ float s_l[64];

    int it = blockIdx.x, hh = blockIdx.y, b = blockIdx.z;
    int i0 = it * 64;
    int tid = threadIdx.x;
    int lane = tid & 31, wid = tid >> 5;
    int ti = tid >> 2, q = tid & 3;

    int gi = b * NN + i0 + ti;
    float srcv = mask[gi] > 0 ? g_src[(size_t)gi * HH + hh] : NEGBIG;
    const int* arow = adj + (size_t)gi * NN + q * 16;
    float lsum = 0.f;

    float c[4][4] = {};
    int m0 = (wid & 3) * 16, n0 = (wid >> 2) * 32;
    int lr = lane & 15, lc = (lane >> 4) * 8;

    int4 aj0, aj1, aj2, aj3;
    uint4 vh0, vh1, vl0, vl1;
    float dv = 0.f;
    {
        const int4* ap = (const int4*)arow;
        aj0 = ap[0]; aj1 = ap[1]; aj2 = ap[2]; aj3 = ap[3];
        const uint4* hp = (const uint4*)(g_hbhi + (size_t)(b * NN + ti) * HD + hh * 64 + q * 16);
        const uint4* lp = (const uint4*)(g_hblo + (size_t)(b * NN + ti) * HD + hh * 64 + q * 16);
        vh0 = hp[0]; vh1 = hp[1];
        vl0 = lp[0]; vl1 = lp[1];
        if (tid < 64) {
            int gj = b * NN + tid;
            float d = g_dst[(size_t)gj * HH + hh];
            dv = mask[gj] > 0 ? d : NEGBIG;
        }
    }

    for (int t = 0; t < 16; t++) {
        __syncthreads();
        *(uint4*)&Vhi[ti][q * 16] = vh0;
        *(uint4*)&Vhi[ti][q * 16 + 8] = vh1;
        *(uint4*)&Vlo[ti][q * 16] = vl0;
        *(uint4*)&Vlo[ti][q * 16 + 8] = vl1;
        if (tid < 64) s_dst[tid] = dv;
        __syncthreads();

        {
            const float4* dp = (const float4*)&s_dst[q * 16];
            float4 d0 = dp[0], d1 = dp[1], d2 = dp[2], d3 = dp[3];
            float p[16];
            float e;
#define SC4(AJ, DV, K)                                                        \
            e = srcv + DV.x; e = fmaxf(e, 0.2f * e); p[K+0] = AJ.x > 0 ? __expf(e) : 0.f; \
            e = srcv + DV.y; e = fmaxf(e, 0.2f * e); p[K+1] = AJ.y > 0 ? __expf(e) : 0.f; \
            e = srcv + DV.z; e = fmaxf(e, 0.2f * e); p[K+2] = AJ.z > 0 ? __expf(e) : 0.f; \
            e = srcv + DV.w; e = fmaxf(e, 0.2f * e); p[K+3] = AJ.w > 0 ? __expf(e) : 0.f;
            SC4(aj0, d0, 0) SC4(aj1, d1, 4) SC4(aj2, d2, 8) SC4(aj3, d3, 12)
#undef SC4
#pragma unroll
            for (int k = 0; k < 16; k++) lsum += p[k];
            u32 hw[8], lw[8];
#pragma unroll
            for (int g = 0; g < 8; g++) {
                float h0 = bhi(p[2 * g]), h1 = bhi(p[2 * g + 1]);
                hw[g] = cvt2(h0, h1);
                lw[g] = cvt2(p[2 * g] - h0, p[2 * g + 1] - h1);
            }
            *(uint4*)&Phi[ti][q * 16] = make_uint4(hw[0], hw[1], hw[2], hw[3]);
            *(uint4*)&Phi[ti][q * 16 + 8] = make_uint4(hw[4], hw[5], hw[6], hw[7]);
            *(uint4*)&Plo[ti][q * 16] = make_uint4(lw[0], lw[1], lw[2], lw[3]);
            *(uint4*)&Plo[ti][q * 16 + 8] = make_uint4(lw[4], lw[5], lw[6], lw[7]);
        }

        if (t < 15) {
            int j0n = (t + 1) * 64;
            const int4* ap = (const int4*)(arow + j0n);
            aj0 = ap[0]; aj1 = ap[1]; aj2 = ap[2]; aj3 = ap[3];
            const uint4* hp = (const uint4*)(g_hbhi + (size_t)(b * NN + j0n + ti) * HD + hh * 64 + q * 16);
            const uint4* lp = (const uint4*)(g_hblo + (size_t)(b * NN + j0n + ti) * HD + hh * 64 + q * 16);
            vh0 = hp[0]; vh1 = hp[1];
            vl0 = lp[0]; vl1 = lp[1];
            if (tid < 64) {
                int gj = b * NN + j0n + tid;
                float d = g_dst[(size_t)gj * HH + hh];
                dv = mask[gj] > 0 ? d : NEGBIG;
            }
        }
        __syncthreads();

#pragma unroll
        for (int ks = 0; ks < 4; ks++) {
            u32 ahi[4], alo[4], bh[8], bl[8];
            ldsm_x4(ahi, smem_u32(&Phi[m0 + lr][ks * 16 + lc]));
            ldsm_x4(alo, smem_u32(&Plo[m0 + lr][ks * 16 + lc]));
            int br = ks * 16 + lr;
            ldsm_x4t(bh,     smem_u32(&Vhi[br][n0 + lc]));
            ldsm_x4t(bh + 4, smem_u32(&Vhi[br][n0 + 16 + lc]));
            ldsm_x4t(bl,     smem_u32(&Vlo[br][n0 + lc]));
            ldsm_x4t(bl + 4, smem_u32(&Vlo[br][n0 + 16 + lc]));
#pragma unroll
            for (int nb = 0; nb < 4; nb++) {
                mma16816(c[nb], ahi, bh[2 * nb], bh[2 * nb + 1]);
                mma16816(c[nb], alo, bh[2 * nb], bh[2 * nb + 1]);
                mma16816(c[nb], ahi, bl[2 * nb], bl[2 * nb + 1]);
            }
        }
    }

    lsum += __shfl_xor_sync(0xffffffffu, lsum, 1);
    lsum += __shfl_xor_sync(0xffffffffu, lsum, 2);
    if (q == 0) s_l[ti] = lsum;
    __syncthreads();
    {
        int r0 = lane >> 2, col0 = (lane & 3) * 2;
        float l0 = s_l[m0 + r0], l1 = s_l[m0 + r0 + 8];
        float inv0 = l0 > 0.f ? 1.0f / l0 : 0.f;
        float inv1 = l1 > 0.f ? 1.0f / l1 : 0.f;
        float* ob = g_att + (size_t)(b * NN + i0 + m0 + r0) * HD + hh * 64 + n0 + col0;
#pragma unroll
        for (int nb = 0; nb < 4; nb++) {
            *(float2*)(ob + nb * 8) = make_float2(c[nb][0] * inv0, c[nb][1] * inv0);
            *(float2*)(ob + 8 * HD + nb * 8) = make_float2(c[nb][2] * inv1, c[nb][3] * inv1);
        }
    }
}

// ---------------------------------------------------------------------------
// Kernel 3: LayerNorm. 32 threads/row, warp-shfl only.  (unchanged)
// ---------------------------------------------------------------------------
__global__ __launch_bounds__(256) void ln_k(const int* __restrict__ mask,
                                            const float* __restrict__ gamma,
                                            const float* __restrict__ beta,
                                            float* __restrict__ out) {
    int row = blockIdx.x * 8 + (threadIdx.x >> 5);
    int lane = threadIdx.x & 31;
    float mf = mask[row] > 0 ? 1.f : 0.f;
    const float* ar = g_att + (size_t)row * HD + lane * 8;
    float4 v0 = ((const float4*)ar)[0];
    float4 v1 = ((const float4*)ar)[1];
    v0.x *= mf; v0.y *= mf; v0.z *= mf; v0.w *= mf;
    v1.x *= mf; v1.y *= mf; v1.z *= mf; v1.w *= mf;
    float s = v0.x + v0.y + v0.z + v0.w + v1.x + v1.y + v1.z + v1.w;
    float s2 = v0.x * v0.x + v0.y * v0.y + v0.z * v0.z + v0.w * v0.w
             + v1.x * v1.x + v1.y * v1.y + v1.z * v1.z + v1.w * v1.w;
#pragma unroll
    for (int o = 16; o > 0; o >>= 1) {
        s += __shfl_xor_sync(0xffffffffu, s, o);
        s2 += __shfl_xor_sync(0xffffffffu, s2, o);
    }
    float mu = s * (1.0f / HD);
    float var = s2 * (1.0f / HD) - mu * mu;
    float rstd = rsqrtf(var + EPSV);
    float4 g0 = ((const float4*)(gamma + lane * 8))[0];
    float4 g1 = ((const float4*)(gamma + lane * 8))[1];
    float4 b0 = ((const float4*)(beta + lane * 8))[0];
    float4 b1 = ((const float4*)(beta + lane * 8))[1];
    float* o = out + (size_t)row * HD + lane * 8;
    ((float4*)o)[0] = make_float4((v0.x - mu) * rstd * g0.x + b0.x,
                                  (v0.y - mu) * rstd * g0.y + b0.y,
                                  (v0.z - mu) * rstd * g0.z + b0.z,
                                  (v0.w - mu) * rstd * g0.w + b0.w);
    ((float4*)o)[1] = make_float4((v1.x - mu) * rstd * g1.x + b1.x,
                                  (v1.y - mu) * rstd * g1.y + b1.y,
                                  (v1.z - mu) * rstd * g1.z + b1.z,
                                  (v1.w - mu) * rstd * g1.w + b1.w);
}

// ---------------------------------------------------------------------------
extern "C" void kernel_launch(void* const* d_in, const int* in_sizes, int n_in,
                              void* d_out, int out_size) {
    const float* x = (const float*)d_in[0];
    const int* adj = (const int*)d_in[1];
    const int* mask = (const int*)d_in[2];
    const float* Wm = (const float*)d_in[3];
    const float* a_src = (const float*)d_in[4];
    const float* a_dst = (const float*)d_in[5];
    const float* gamma = (const float*)d_in[6];
    const float* beta = (const float*)d_in[7];
    float* out = (float*)d_out;

    dim3 gg(BB * NN / 128, HD / 128);
    gemm_k<<<gg, 256>>>(x, Wm, a_src, a_dst);
    dim3 ga(NN / 64, HH, BB);
    attn_k<<<ga, 256>>>(adj, mask);
    ln_k<<<BB * NN / 8, 256>>>(mask, gamma, beta, out);
}